// round 1
// baseline (speedup 1.0000x reference)
#include <cuda_runtime.h>
#include <math.h>

#define BATCH   4
#define SEQLEN  4096
#define DMODEL  1024
#define DINNER  2048
#define DSTATE  16
#define DCONV   4
#define NTOK    (BATCH*SEQLEN)      /* 16384 */
#define CHUNK   256
#define NCH     (SEQLEN/CHUNK)      /* 16 */

/* ---------------- scratch (device globals; no allocation allowed) ---------------- */
__device__ float g_xinner[NTOK*DINNER];
__device__ float g_xc    [NTOK*DINNER];
__device__ float g_delta [NTOK*DINNER];
__device__ float g_Bm    [NTOK*DSTATE];
__device__ float g_Cm    [NTOK*DSTATE];
__device__ float g_y     [NTOK*DINNER];
__device__ float g_ap    [BATCH*DINNER*NCH*DSTATE];
__device__ float g_he    [BATCH*DINNER*NCH*DSTATE];

/* ---------------- classic 128x128x8 fp32 GEMM: C[M,N] = A[M,K] @ W[N,K]^T -------- */
__global__ __launch_bounds__(256)
void sgemm128(int M, int N, int K,
              const float* __restrict__ A,
              const float* __restrict__ W,
              float* __restrict__ C)
{
    const int BM = 128, BN = 128, BK = 8, TM = 8, TN = 8;
    __shared__ float As[BK][BM];
    __shared__ float Ws[BK][BN];

    const int tid = threadIdx.x;
    const int tx  = tid & 15;       // 16 cols of threads
    const int ty  = tid >> 4;       // 16 rows of threads
    const int mb  = blockIdx.y * BM;
    const int nb  = blockIdx.x * BN;

    const int lrow = tid >> 1;          // 0..127
    const int lcol = (tid & 1) * 4;     // 0 or 4

    const float* Ap = A + (size_t)(mb + lrow) * K + lcol;
    const float* Wp = W + (size_t)(nb + lrow) * K + lcol;

    float acc[TM][TN];
    #pragma unroll
    for (int i = 0; i < TM; ++i)
        #pragma unroll
        for (int j = 0; j < TN; ++j) acc[i][j] = 0.f;

    for (int k0 = 0; k0 < K; k0 += BK) {
        float4 av = *reinterpret_cast<const float4*>(Ap + k0);
        float4 wv = *reinterpret_cast<const float4*>(Wp + k0);
        As[lcol+0][lrow] = av.x; As[lcol+1][lrow] = av.y;
        As[lcol+2][lrow] = av.z; As[lcol+3][lrow] = av.w;
        Ws[lcol+0][lrow] = wv.x; Ws[lcol+1][lrow] = wv.y;
        Ws[lcol+2][lrow] = wv.z; Ws[lcol+3][lrow] = wv.w;
        __syncthreads();

        #pragma unroll
        for (int k = 0; k < BK; ++k) {
            float4 a0 = *reinterpret_cast<const float4*>(&As[k][ty*TM]);
            float4 a1 = *reinterpret_cast<const float4*>(&As[k][ty*TM+4]);
            float4 w0 = *reinterpret_cast<const float4*>(&Ws[k][tx*TN]);
            float4 w1 = *reinterpret_cast<const float4*>(&Ws[k][tx*TN+4]);
            float ar[8] = {a0.x,a0.y,a0.z,a0.w,a1.x,a1.y,a1.z,a1.w};
            float wr[8] = {w0.x,w0.y,w0.z,w0.w,w1.x,w1.y,w1.z,w1.w};
            #pragma unroll
            for (int i = 0; i < TM; ++i)
                #pragma unroll
                for (int j = 0; j < TN; ++j)
                    acc[i][j] = fmaf(ar[i], wr[j], acc[i][j]);
        }
        __syncthreads();
    }

    #pragma unroll
    for (int i = 0; i < TM; ++i) {
        float* Cp = C + (size_t)(mb + ty*TM + i) * N + nb + tx*TN;
        float4 v0 = make_float4(acc[i][0], acc[i][1], acc[i][2], acc[i][3]);
        float4 v1 = make_float4(acc[i][4], acc[i][5], acc[i][6], acc[i][7]);
        *reinterpret_cast<float4*>(Cp)     = v0;
        *reinterpret_cast<float4*>(Cp + 4) = v1;
    }
}

/* ------------- skinny GEMM: B = X @ BW^T (N=16), C = X @ CW^T (N=16) ------------- */
__global__ __launch_bounds__(256)
void skinny_bc(const float* __restrict__ X,
               const float* __restrict__ BW,
               const float* __restrict__ CW,
               float* __restrict__ Bm,
               float* __restrict__ Cm)
{
    __shared__ float Xs[128][33];
    __shared__ float Ws[32][33];
    const int tid = threadIdx.x;
    const int n = tid & 31;       // output column 0..31 (B:0-15, C:16-31)
    const int g = tid >> 5;       // 0..7 token group
    const int m0 = blockIdx.x * 128;

    float acc[16];
    #pragma unroll
    for (int i = 0; i < 16; ++i) acc[i] = 0.f;

    for (int k0 = 0; k0 < DMODEL; k0 += 32) {
        for (int f = tid; f < 1024; f += 256) {
            int r = f >> 3, c = (f & 7) * 4;
            float4 v = *reinterpret_cast<const float4*>(X + (size_t)(m0 + r) * DMODEL + k0 + c);
            Xs[r][c] = v.x; Xs[r][c+1] = v.y; Xs[r][c+2] = v.z; Xs[r][c+3] = v.w;
        }
        {
            int r = tid >> 3, c = (tid & 7) * 4;
            const float* src = (r < 16) ? (BW + (size_t)r * DMODEL)
                                        : (CW + (size_t)(r - 16) * DMODEL);
            float4 v = *reinterpret_cast<const float4*>(src + k0 + c);
            Ws[r][c] = v.x; Ws[r][c+1] = v.y; Ws[r][c+2] = v.z; Ws[r][c+3] = v.w;
        }
        __syncthreads();
        #pragma unroll
        for (int kk = 0; kk < 32; ++kk) {
            float w = Ws[n][kk];
            #pragma unroll
            for (int i = 0; i < 16; ++i)
                acc[i] = fmaf(Xs[g*16 + i][kk], w, acc[i]);
        }
        __syncthreads();
    }

    float* dst = (n < 16) ? Bm : Cm;
    const int nn = n & 15;
    #pragma unroll
    for (int i = 0; i < 16; ++i)
        dst[(size_t)(m0 + g*16 + i) * DSTATE + nn] = acc[i];
}

/* ---------- depthwise causal conv1d + bias + SiLU; softplus(delta + bias) -------- */
__global__ void conv_silu_softplus(const float* __restrict__ xin,
                                   const float* __restrict__ cw,
                                   const float* __restrict__ cb,
                                   const float* __restrict__ dtb,
                                   float* __restrict__ xc,
                                   float* __restrict__ delta)
{
    const int d  = blockIdx.x * blockDim.x + threadIdx.x;
    const int b  = blockIdx.z;
    const int t0 = blockIdx.y * 512;

    const float w0 = cw[d*4+0], w1 = cw[d*4+1], w2 = cw[d*4+2], w3 = cw[d*4+3];
    const float bias = cb[d];
    const float db   = dtb[d];

    const float* base = xin + (size_t)b * SEQLEN * DINNER + d;
    float xm3 = (t0 - 3 >= 0) ? base[(size_t)(t0-3) * DINNER] : 0.f;
    float xm2 = (t0 - 2 >= 0) ? base[(size_t)(t0-2) * DINNER] : 0.f;
    float xm1 = (t0 - 1 >= 0) ? base[(size_t)(t0-1) * DINNER] : 0.f;

    for (int t = t0; t < t0 + 512; ++t) {
        const size_t gidx = ((size_t)b * SEQLEN + t) * DINNER + d;
        float cur = base[(size_t)t * DINNER];
        float v = fmaf(w0, xm3, fmaf(w1, xm2, fmaf(w2, xm1, fmaf(w3, cur, bias))));
        float sig = 1.f / (1.f + __expf(-v));
        xc[gidx] = v * sig;
        xm3 = xm2; xm2 = xm1; xm1 = cur;

        float z = delta[gidx] + db;
        delta[gidx] = (z > 20.f) ? z : log1pf(__expf(z));
    }
}

/* --------------- scan pass 1: per-chunk decay products + local h_end ------------- */
__global__ __launch_bounds__(128)
void scan_pass1(const float* __restrict__ delta, const float* __restrict__ xc,
                const float* __restrict__ Bm, const float* __restrict__ A_log,
                float* __restrict__ ap_out, float* __restrict__ he_out)
{
    __shared__ float Bs[CHUNK*DSTATE];
    const int tid = threadIdx.x;
    const int d = blockIdx.x * 128 + tid;
    const int c = blockIdx.y, b = blockIdx.z;

    const float* Bsrc = Bm + ((size_t)b * SEQLEN + (size_t)c * CHUNK) * DSTATE;
    for (int i = tid; i < CHUNK*DSTATE; i += 128) Bs[i] = Bsrc[i];
    __syncthreads();

    float A[DSTATE];
    #pragma unroll
    for (int s = 0; s < DSTATE; ++s) A[s] = -expf(A_log[d*DSTATE + s]);

    float h[DSTATE], ap[DSTATE];
    #pragma unroll
    for (int s = 0; s < DSTATE; ++s) { h[s] = 0.f; ap[s] = 1.f; }

    const float* dptr = delta + ((size_t)b * SEQLEN + (size_t)c * CHUNK) * DINNER + d;
    const float* xptr = xc    + ((size_t)b * SEQLEN + (size_t)c * CHUNK) * DINNER + d;

    for (int tl = 0; tl < CHUNK; ++tl) {
        float dt = dptr[(size_t)tl * DINNER];
        float xv = xptr[(size_t)tl * DINNER];
        float dx = dt * xv;
        #pragma unroll
        for (int s = 0; s < DSTATE; ++s) {
            float a = __expf(dt * A[s]);
            ap[s] *= a;
            h[s] = fmaf(a, h[s], dx * Bs[tl*DSTATE + s]);
        }
    }

    const size_t o = (((size_t)b * DINNER + d) * NCH + c) * DSTATE;
    #pragma unroll
    for (int s = 0; s < DSTATE; ++s) { ap_out[o+s] = ap[s]; he_out[o+s] = h[s]; }
}

/* ------- scan pass 2: sequential stitch over chunks; he buffer -> chunk inits ---- */
__global__ void scan_pass2(const float* __restrict__ ap, float* __restrict__ he)
{
    const int idx = blockIdx.x * blockDim.x + threadIdx.x;  // b*DINNER + d
    if (idx >= BATCH*DINNER) return;
    float h[DSTATE];
    #pragma unroll
    for (int s = 0; s < DSTATE; ++s) h[s] = 0.f;
    for (int c = 0; c < NCH; ++c) {
        const size_t o = ((size_t)idx * NCH + c) * DSTATE;
        #pragma unroll
        for (int s = 0; s < DSTATE; ++s) {
            float hin = h[s];
            h[s] = fmaf(ap[o+s], hin, he[o+s]);
            he[o+s] = hin;                 // overwrite with chunk-initial state
        }
    }
}

/* --------------- scan pass 3: recompute with correct init, emit y ---------------- */
__global__ __launch_bounds__(128)
void scan_pass3(const float* __restrict__ delta, const float* __restrict__ xc,
                const float* __restrict__ Bm, const float* __restrict__ Cm,
                const float* __restrict__ A_log, const float* __restrict__ Dv,
                const float* __restrict__ hinit, float* __restrict__ y)
{
    __shared__ float Bs[CHUNK*DSTATE];
    __shared__ float Cs[CHUNK*DSTATE];
    const int tid = threadIdx.x;
    const int d = blockIdx.x * 128 + tid;
    const int c = blockIdx.y, b = blockIdx.z;

    const float* Bsrc = Bm + ((size_t)b * SEQLEN + (size_t)c * CHUNK) * DSTATE;
    const float* Csrc = Cm + ((size_t)b * SEQLEN + (size_t)c * CHUNK) * DSTATE;
    for (int i = tid; i < CHUNK*DSTATE; i += 128) { Bs[i] = Bsrc[i]; Cs[i] = Csrc[i]; }
    __syncthreads();

    float A[DSTATE];
    #pragma unroll
    for (int s = 0; s < DSTATE; ++s) A[s] = -expf(A_log[d*DSTATE + s]);

    float h[DSTATE];
    const size_t oinit = (((size_t)b * DINNER + d) * NCH + c) * DSTATE;
    #pragma unroll
    for (int s = 0; s < DSTATE; ++s) h[s] = hinit[oinit + s];

    const float Dd = Dv[d];
    const float* dptr = delta + ((size_t)b * SEQLEN + (size_t)c * CHUNK) * DINNER + d;
    const float* xptr = xc    + ((size_t)b * SEQLEN + (size_t)c * CHUNK) * DINNER + d;
    float* yptr       = y     + ((size_t)b * SEQLEN + (size_t)c * CHUNK) * DINNER + d;

    for (int tl = 0; tl < CHUNK; ++tl) {
        float dt = dptr[(size_t)tl * DINNER];
        float xv = xptr[(size_t)tl * DINNER];
        float dx = dt * xv;
        float acc = 0.f;
        #pragma unroll
        for (int s = 0; s < DSTATE; ++s) {
            float a = __expf(dt * A[s]);
            h[s] = fmaf(a, h[s], dx * Bs[tl*DSTATE + s]);
            acc = fmaf(h[s], Cs[tl*DSTATE + s], acc);
        }
        yptr[(size_t)tl * DINNER] = fmaf(Dd, xv, acc);
    }
}

/* -------------------------------- launcher --------------------------------------- */
extern "C" void kernel_launch(void* const* d_in, const int* in_sizes, int n_in,
                              void* d_out, int out_size)
{
    const float* x         = (const float*)d_in[0];
    const float* x_proj_w  = (const float*)d_in[1];
    const float* dt_proj_w = (const float*)d_in[2];
    const float* dt_proj_b = (const float*)d_in[3];
    const float* A_log     = (const float*)d_in[4];
    const float* Dvec      = (const float*)d_in[5];
    const float* B_proj_w  = (const float*)d_in[6];
    const float* C_proj_w  = (const float*)d_in[7];
    const float* conv_w    = (const float*)d_in[8];
    const float* conv_b    = (const float*)d_in[9];
    const float* out_proj_w= (const float*)d_in[10];
    float* out = (float*)d_out;

    float *xinner, *xc, *delta, *Bm, *Cm, *y, *ap, *he;
    cudaGetSymbolAddress((void**)&xinner, g_xinner);
    cudaGetSymbolAddress((void**)&xc,     g_xc);
    cudaGetSymbolAddress((void**)&delta,  g_delta);
    cudaGetSymbolAddress((void**)&Bm,     g_Bm);
    cudaGetSymbolAddress((void**)&Cm,     g_Cm);
    cudaGetSymbolAddress((void**)&y,      g_y);
    cudaGetSymbolAddress((void**)&ap,     g_ap);
    cudaGetSymbolAddress((void**)&he,     g_he);

    // x_inner = x @ x_proj_w^T ; delta_pre = x @ dt_proj_w^T
    sgemm128<<<dim3(DINNER/128, NTOK/128), 256>>>(NTOK, DINNER, DMODEL, x, x_proj_w, xinner);
    sgemm128<<<dim3(DINNER/128, NTOK/128), 256>>>(NTOK, DINNER, DMODEL, x, dt_proj_w, delta);

    // B, C projections (N=16 each)
    skinny_bc<<<NTOK/128, 256>>>(x, B_proj_w, C_proj_w, Bm, Cm);

    // conv + SiLU (-> xc), softplus(delta + bias) in place
    conv_silu_softplus<<<dim3(DINNER/256, SEQLEN/512, BATCH), 256>>>(
        xinner, conv_w, conv_b, dt_proj_b, xc, delta);

    // chunked selective scan
    scan_pass1<<<dim3(DINNER/128, NCH, BATCH), 128>>>(delta, xc, Bm, A_log, ap, he);
    scan_pass2<<<(BATCH*DINNER)/128, 128>>>(ap, he);
    scan_pass3<<<dim3(DINNER/128, NCH, BATCH), 128>>>(delta, xc, Bm, Cm, A_log, Dvec, he, y);

    // out = y @ out_proj_w^T
    sgemm128<<<dim3(DMODEL/128, NTOK/128), 256>>>(NTOK, DMODEL, DINNER, y, out_proj_w, out);
}

// round 3
// speedup vs baseline: 2.1013x; 2.1013x over previous
#include <cuda_runtime.h>
#include <cuda_bf16.h>
#include <math.h>
#include <stdint.h>

#define BATCH   4
#define SEQLEN  4096
#define DMODEL  1024
#define DINNER  2048
#define DSTATE  16
#define NTOK    (BATCH*SEQLEN)      /* 16384 */
#define CHUNK   256
#define NCH     (SEQLEN/CHUNK)      /* 16 */

/* ---------------- scratch (device globals; no allocation allowed) ---------------- */
__device__ float g_xinner[NTOK*DINNER];
__device__ float g_xc    [NTOK*DINNER];
__device__ float g_delta [NTOK*DINNER];
__device__ float g_Bm    [NTOK*DSTATE];
__device__ float g_Cm    [NTOK*DSTATE];
__device__ float g_y     [NTOK*DINNER];
__device__ float g_ap    [BATCH*DINNER*NCH*DSTATE];
__device__ float g_he    [BATCH*DINNER*NCH*DSTATE];
__device__ __nv_bfloat16 g_xhi[NTOK*DMODEL];
__device__ __nv_bfloat16 g_xlo[NTOK*DMODEL];
__device__ __nv_bfloat16 g_whi[DINNER*DMODEL];
__device__ __nv_bfloat16 g_wlo[DINNER*DMODEL];
__device__ __nv_bfloat16 g_yhi[NTOK*DINNER];
__device__ __nv_bfloat16 g_ylo[NTOK*DINNER];

/* ============================ PTX helpers ======================================== */
__device__ __forceinline__ uint32_t smem_u32(const void* p){
    uint32_t a;
    asm("{ .reg .u64 t; cvta.to.shared.u64 t, %1; cvt.u32.u64 %0, t; }" : "=r"(a) : "l"(p));
    return a;
}
__device__ __forceinline__ void cpa16(uint32_t dst, const void* src){
    asm volatile("cp.async.cg.shared.global [%0], [%1], 16;" :: "r"(dst), "l"(src));
}
__device__ __forceinline__ void ldsm4(uint32_t& r0, uint32_t& r1, uint32_t& r2, uint32_t& r3,
                                      uint32_t addr){
    asm volatile("ldmatrix.sync.aligned.m8n8.x4.shared.b16 {%0,%1,%2,%3}, [%4];"
                 : "=r"(r0), "=r"(r1), "=r"(r2), "=r"(r3) : "r"(addr));
}
__device__ __forceinline__ void ldsm2(uint32_t& r0, uint32_t& r1, uint32_t addr){
    asm volatile("ldmatrix.sync.aligned.m8n8.x2.shared.b16 {%0,%1}, [%2];"
                 : "=r"(r0), "=r"(r1) : "r"(addr));
}
__device__ __forceinline__ void mma16816(float* c, const uint32_t* a, const uint32_t* b){
    asm volatile(
        "mma.sync.aligned.m16n8k16.row.col.f32.bf16.bf16.f32 "
        "{%0,%1,%2,%3}, {%4,%5,%6,%7}, {%8,%9}, {%0,%1,%2,%3};"
        : "+f"(c[0]), "+f"(c[1]), "+f"(c[2]), "+f"(c[3])
        : "r"(a[0]), "r"(a[1]), "r"(a[2]), "r"(a[3]), "r"(b[0]), "r"(b[1]));
}

/* ====================== fp32 -> (bf16 hi, bf16 lo) split ========================= */
__global__ __launch_bounds__(256)
void split_bf16(const float* __restrict__ src,
                __nv_bfloat16* __restrict__ hi,
                __nv_bfloat16* __restrict__ lo, int n4)
{
    int i = blockIdx.x * 256 + threadIdx.x;
    if (i >= n4) return;
    float4 v = reinterpret_cast<const float4*>(src)[i];
    __nv_bfloat16 h0 = __float2bfloat16(v.x);
    __nv_bfloat16 h1 = __float2bfloat16(v.y);
    __nv_bfloat16 h2 = __float2bfloat16(v.z);
    __nv_bfloat16 h3 = __float2bfloat16(v.w);
    __nv_bfloat16 l0 = __float2bfloat16(v.x - __bfloat162float(h0));
    __nv_bfloat16 l1 = __float2bfloat16(v.y - __bfloat162float(h1));
    __nv_bfloat16 l2 = __float2bfloat16(v.z - __bfloat162float(h2));
    __nv_bfloat16 l3 = __float2bfloat16(v.w - __bfloat162float(h3));
    __nv_bfloat162* hp = reinterpret_cast<__nv_bfloat162*>(hi);
    __nv_bfloat162* lp = reinterpret_cast<__nv_bfloat162*>(lo);
    hp[2*i]   = __halves2bfloat162(h0, h1);
    hp[2*i+1] = __halves2bfloat162(h2, h3);
    lp[2*i]   = __halves2bfloat162(l0, l1);
    lp[2*i+1] = __halves2bfloat162(l2, l3);
}

/* ============ HMMA bf16x3 GEMM: C[M,N] = A[M,K] @ W[N,K]^T (fp32 out) ============ */
/* 128x128 CTA tile, BK=32, 4-stage cp.async pipeline, mma.sync m16n8k16.           */
#define ROWB      80                 /* 64B data + 16B pad, conflict-free ldmatrix  */
#define TILE_B    (128*ROWB)         /* 10240 */
#define STAGE_B   (4*TILE_B)         /* 40960: Ah, Al, Wh, Wl */
#define NSTAGE    4
#define SMEM_GEMM (NSTAGE*STAGE_B)   /* 163840 */

__device__ __forceinline__ void load_stage(
    uint32_t stage, int tid, int m0, int n0, int k0, int K,
    const __nv_bfloat16* __restrict__ Ah, const __nv_bfloat16* __restrict__ Al,
    const __nv_bfloat16* __restrict__ Wh, const __nv_bfloat16* __restrict__ Wl)
{
    #pragma unroll
    for (int i = 0; i < 8; ++i) {
        const int idx  = tid + 256 * i;
        const int tile = idx >> 9;          /* 512 chunks per tile */
        const int rem  = idx & 511;
        const int row  = rem >> 2;
        const int c    = rem & 3;
        const __nv_bfloat16* gp;
        if      (tile == 0) gp = Ah + (size_t)(m0 + row) * K + k0 + c*8;
        else if (tile == 1) gp = Al + (size_t)(m0 + row) * K + k0 + c*8;
        else if (tile == 2) gp = Wh + (size_t)(n0 + row) * K + k0 + c*8;
        else                gp = Wl + (size_t)(n0 + row) * K + k0 + c*8;
        cpa16(stage + tile * TILE_B + row * ROWB + c * 16, gp);
    }
    asm volatile("cp.async.commit_group;" ::: "memory");
}

__global__ void __launch_bounds__(256, 1)
hmma_gemm(int M, int N, int K,
          const __nv_bfloat16* __restrict__ Ah, const __nv_bfloat16* __restrict__ Al,
          const __nv_bfloat16* __restrict__ Wh, const __nv_bfloat16* __restrict__ Wl,
          float* __restrict__ C)
{
    extern __shared__ char smem[];
    const uint32_t sb = smem_u32(smem);
    const int tid  = threadIdx.x;
    const int wid  = tid >> 5;
    const int lane = tid & 31;
    const int wy   = wid & 1;          /* 2 warps along M (64 rows each)  */
    const int wx   = wid >> 1;         /* 4 warps along N (32 cols each)  */
    const int m0 = blockIdx.y * 128, n0 = blockIdx.x * 128;

    float acc[4][4][4];
    #pragma unroll
    for (int i = 0; i < 4; ++i)
        #pragma unroll
        for (int j = 0; j < 4; ++j)
            #pragma unroll
            for (int e = 0; e < 4; ++e) acc[i][j][e] = 0.f;

    const int KT = K >> 5;

    load_stage(sb + 0*STAGE_B, tid, m0, n0,  0, K, Ah, Al, Wh, Wl);
    load_stage(sb + 1*STAGE_B, tid, m0, n0, 32, K, Ah, Al, Wh, Wl);
    load_stage(sb + 2*STAGE_B, tid, m0, n0, 64, K, Ah, Al, Wh, Wl);

    /* per-lane ldmatrix address components */
    const int arow = lane & 15;             /* A: row within 16-row block   */
    const int acol = (lane >> 4) * 16;      /* A: 16B column selector       */
    const int brow = lane & 7;              /* B: row within 8-row block    */
    const int bcol = ((lane >> 3) & 1) * 16;

    for (int kt = 0; kt < KT; ++kt) {
        asm volatile("cp.async.wait_group 2;" ::: "memory");
        __syncthreads();

        if (kt + 3 < KT)
            load_stage(sb + ((kt + 3) & 3) * STAGE_B, tid, m0, n0, (kt + 3) * 32,
                       K, Ah, Al, Wh, Wl);

        const uint32_t st = sb + (kt & 3) * STAGE_B;
        #pragma unroll
        for (int ks = 0; ks < 2; ++ks) {
            uint32_t ah[4][4], al[4][4], bh[4][2], bl[4][2];
            #pragma unroll
            for (int mi = 0; mi < 4; ++mi) {
                uint32_t ra = st + (uint32_t)((wy*64 + mi*16 + arow) * ROWB + ks*32 + acol);
                ldsm4(ah[mi][0], ah[mi][1], ah[mi][2], ah[mi][3], ra);
                ldsm4(al[mi][0], al[mi][1], al[mi][2], al[mi][3], ra + TILE_B);
            }
            #pragma unroll
            for (int ni = 0; ni < 4; ++ni) {
                uint32_t rb = st + 2*TILE_B +
                              (uint32_t)((wx*32 + ni*8 + brow) * ROWB + ks*32 + bcol);
                ldsm2(bh[ni][0], bh[ni][1], rb);
                ldsm2(bl[ni][0], bl[ni][1], rb + TILE_B);
            }
            #pragma unroll
            for (int mi = 0; mi < 4; ++mi)
                #pragma unroll
                for (int ni = 0; ni < 4; ++ni) {
                    mma16816(acc[mi][ni], ah[mi], bh[ni]);
                    mma16816(acc[mi][ni], ah[mi], bl[ni]);
                    mma16816(acc[mi][ni], al[mi], bh[ni]);
                }
        }
        __syncthreads();
    }

    /* epilogue: fragment -> global (float2 per mma sub-row) */
    const int r0 = lane >> 2;
    const int c0 = (lane & 3) * 2;
    #pragma unroll
    for (int mi = 0; mi < 4; ++mi)
        #pragma unroll
        for (int ni = 0; ni < 4; ++ni) {
            const int row = m0 + wy*64 + mi*16 + r0;
            const int col = n0 + wx*32 + ni*8 + c0;
            *reinterpret_cast<float2*>(C + (size_t)row * N + col) =
                make_float2(acc[mi][ni][0], acc[mi][ni][1]);
            *reinterpret_cast<float2*>(C + (size_t)(row + 8) * N + col) =
                make_float2(acc[mi][ni][2], acc[mi][ni][3]);
        }
}

/* ------------- skinny GEMM: B = X @ BW^T (N=16), C = X @ CW^T (N=16) ------------- */
__global__ __launch_bounds__(256)
void skinny_bc(const float* __restrict__ X,
               const float* __restrict__ BW,
               const float* __restrict__ CW,
               float* __restrict__ Bm,
               float* __restrict__ Cm)
{
    __shared__ float Xs[128][33];
    __shared__ float Ws[32][33];
    const int tid = threadIdx.x;
    const int n = tid & 31;
    const int g = tid >> 5;
    const int m0 = blockIdx.x * 128;

    float acc[16];
    #pragma unroll
    for (int i = 0; i < 16; ++i) acc[i] = 0.f;

    for (int k0 = 0; k0 < DMODEL; k0 += 32) {
        for (int f = tid; f < 1024; f += 256) {
            int r = f >> 3, c = (f & 7) * 4;
            float4 v = *reinterpret_cast<const float4*>(X + (size_t)(m0 + r) * DMODEL + k0 + c);
            Xs[r][c] = v.x; Xs[r][c+1] = v.y; Xs[r][c+2] = v.z; Xs[r][c+3] = v.w;
        }
        {
            int r = tid >> 3, c = (tid & 7) * 4;
            const float* src = (r < 16) ? (BW + (size_t)r * DMODEL)
                                        : (CW + (size_t)(r - 16) * DMODEL);
            float4 v = *reinterpret_cast<const float4*>(src + k0 + c);
            Ws[r][c] = v.x; Ws[r][c+1] = v.y; Ws[r][c+2] = v.z; Ws[r][c+3] = v.w;
        }
        __syncthreads();
        #pragma unroll
        for (int kk = 0; kk < 32; ++kk) {
            float w = Ws[n][kk];
            #pragma unroll
            for (int i = 0; i < 16; ++i)
                acc[i] = fmaf(Xs[g*16 + i][kk], w, acc[i]);
        }
        __syncthreads();
    }

    float* dst = (n < 16) ? Bm : Cm;
    const int nn = n & 15;
    #pragma unroll
    for (int i = 0; i < 16; ++i)
        dst[(size_t)(m0 + g*16 + i) * DSTATE + nn] = acc[i];
}

/* ---------- depthwise causal conv1d + bias + SiLU; softplus(delta + bias) -------- */
#define CTS 64
__global__ void conv_silu_softplus(const float* __restrict__ xin,
                                   const float* __restrict__ cw,
                                   const float* __restrict__ cb,
                                   const float* __restrict__ dtb,
                                   float* __restrict__ xc,
                                   float* __restrict__ delta)
{
    const int d  = blockIdx.x * blockDim.x + threadIdx.x;
    const int b  = blockIdx.z;
    const int t0 = blockIdx.y * CTS;

    const float w0 = cw[d*4+0], w1 = cw[d*4+1], w2 = cw[d*4+2], w3 = cw[d*4+3];
    const float bias = cb[d];
    const float db   = dtb[d];

    const float* base = xin + (size_t)b * SEQLEN * DINNER + d;
    float xm3 = (t0 - 3 >= 0) ? base[(size_t)(t0-3) * DINNER] : 0.f;
    float xm2 = (t0 - 2 >= 0) ? base[(size_t)(t0-2) * DINNER] : 0.f;
    float xm1 = (t0 - 1 >= 0) ? base[(size_t)(t0-1) * DINNER] : 0.f;

    for (int t = t0; t < t0 + CTS; ++t) {
        const size_t gidx = ((size_t)b * SEQLEN + t) * DINNER + d;
        float cur = base[(size_t)t * DINNER];
        float v = fmaf(w0, xm3, fmaf(w1, xm2, fmaf(w2, xm1, fmaf(w3, cur, bias))));
        float sig = 1.f / (1.f + __expf(-v));
        xc[gidx] = v * sig;
        xm3 = xm2; xm2 = xm1; xm1 = cur;

        float z = delta[gidx] + db;
        delta[gidx] = (z > 20.f) ? z : log1pf(__expf(z));
    }
}

/* --------------- scan pass 1: per-chunk decay products + local h_end ------------- */
__global__ __launch_bounds__(128)
void scan_pass1(const float* __restrict__ delta, const float* __restrict__ xc,
                const float* __restrict__ Bm, const float* __restrict__ A_log,
                float* __restrict__ ap_out, float* __restrict__ he_out)
{
    __shared__ float Bs[CHUNK*DSTATE];
    const int tid = threadIdx.x;
    const int d = blockIdx.x * 128 + tid;
    const int c = blockIdx.y, b = blockIdx.z;

    const float* Bsrc = Bm + ((size_t)b * SEQLEN + (size_t)c * CHUNK) * DSTATE;
    for (int i = tid; i < CHUNK*DSTATE; i += 128) Bs[i] = Bsrc[i];
    __syncthreads();

    float A[DSTATE];
    #pragma unroll
    for (int s = 0; s < DSTATE; ++s) A[s] = -expf(A_log[d*DSTATE + s]);

    float h[DSTATE], ap[DSTATE];
    #pragma unroll
    for (int s = 0; s < DSTATE; ++s) { h[s] = 0.f; ap[s] = 1.f; }

    const float* dptr = delta + ((size_t)b * SEQLEN + (size_t)c * CHUNK) * DINNER + d;
    const float* xptr = xc    + ((size_t)b * SEQLEN + (size_t)c * CHUNK) * DINNER + d;

    for (int tl = 0; tl < CHUNK; ++tl) {
        float dt = dptr[(size_t)tl * DINNER];
        float xv = xptr[(size_t)tl * DINNER];
        float dx = dt * xv;
        #pragma unroll
        for (int s = 0; s < DSTATE; ++s) {
            float a = __expf(dt * A[s]);
            ap[s] *= a;
            h[s] = fmaf(a, h[s], dx * Bs[tl*DSTATE + s]);
        }
    }

    const size_t o = (((size_t)b * DINNER + d) * NCH + c) * DSTATE;
    #pragma unroll
    for (int s = 0; s < DSTATE; ++s) { ap_out[o+s] = ap[s]; he_out[o+s] = h[s]; }
}

/* ------- scan pass 2: sequential stitch over chunks; he buffer -> chunk inits ---- */
__global__ void scan_pass2(const float* __restrict__ ap, float* __restrict__ he)
{
    const int idx = blockIdx.x * blockDim.x + threadIdx.x;
    if (idx >= BATCH*DINNER) return;
    float h[DSTATE];
    #pragma unroll
    for (int s = 0; s < DSTATE; ++s) h[s] = 0.f;
    for (int c = 0; c < NCH; ++c) {
        const size_t o = ((size_t)idx * NCH + c) * DSTATE;
        #pragma unroll
        for (int s = 0; s < DSTATE; ++s) {
            float hin = h[s];
            h[s] = fmaf(ap[o+s], hin, he[o+s]);
            he[o+s] = hin;
        }
    }
}

/* --------------- scan pass 3: recompute with correct init, emit y ---------------- */
__global__ __launch_bounds__(128)
void scan_pass3(const float* __restrict__ delta, const float* __restrict__ xc,
                const float* __restrict__ Bm, const float* __restrict__ Cm,
                const float* __restrict__ A_log, const float* __restrict__ Dv,
                const float* __restrict__ hinit, float* __restrict__ y)
{
    __shared__ float Bs[CHUNK*DSTATE];
    __shared__ float Cs[CHUNK*DSTATE];
    const int tid = threadIdx.x;
    const int d = blockIdx.x * 128 + tid;
    const int c = blockIdx.y, b = blockIdx.z;

    const float* Bsrc = Bm + ((size_t)b * SEQLEN + (size_t)c * CHUNK) * DSTATE;
    const float* Csrc = Cm + ((size_t)b * SEQLEN + (size_t)c * CHUNK) * DSTATE;
    for (int i = tid; i < CHUNK*DSTATE; i += 128) { Bs[i] = Bsrc[i]; Cs[i] = Csrc[i]; }
    __syncthreads();

    float A[DSTATE];
    #pragma unroll
    for (int s = 0; s < DSTATE; ++s) A[s] = -expf(A_log[d*DSTATE + s]);

    float h[DSTATE];
    const size_t oinit = (((size_t)b * DINNER + d) * NCH + c) * DSTATE;
    #pragma unroll
    for (int s = 0; s < DSTATE; ++s) h[s] = hinit[oinit + s];

    const float Dd = Dv[d];
    const float* dptr = delta + ((size_t)b * SEQLEN + (size_t)c * CHUNK) * DINNER + d;
    const float* xptr = xc    + ((size_t)b * SEQLEN + (size_t)c * CHUNK) * DINNER + d;
    float* yptr       = y     + ((size_t)b * SEQLEN + (size_t)c * CHUNK) * DINNER + d;

    for (int tl = 0; tl < CHUNK; ++tl) {
        float dt = dptr[(size_t)tl * DINNER];
        float xv = xptr[(size_t)tl * DINNER];
        float dx = dt * xv;
        float acc = 0.f;
        #pragma unroll
        for (int s = 0; s < DSTATE; ++s) {
            float a = __expf(dt * A[s]);
            h[s] = fmaf(a, h[s], dx * Bs[tl*DSTATE + s]);
            acc = fmaf(h[s], Cs[tl*DSTATE + s], acc);
        }
        yptr[(size_t)tl * DINNER] = fmaf(Dd, xv, acc);
    }
}

/* -------------------------------- launcher --------------------------------------- */
extern "C" void kernel_launch(void* const* d_in, const int* in_sizes, int n_in,
                              void* d_out, int out_size)
{
    const float* x         = (const float*)d_in[0];
    const float* x_proj_w  = (const float*)d_in[1];
    const float* dt_proj_w = (const float*)d_in[2];
    const float* dt_proj_b = (const float*)d_in[3];
    const float* A_log     = (const float*)d_in[4];
    const float* Dvec      = (const float*)d_in[5];
    const float* B_proj_w  = (const float*)d_in[6];
    const float* C_proj_w  = (const float*)d_in[7];
    const float* conv_w    = (const float*)d_in[8];
    const float* conv_b    = (const float*)d_in[9];
    const float* out_proj_w= (const float*)d_in[10];
    float* out = (float*)d_out;

    float *xinner, *xc, *delta, *Bm, *Cm, *y, *ap, *he;
    __nv_bfloat16 *xhi, *xlo, *whi, *wlo, *yhi, *ylo;
    cudaGetSymbolAddress((void**)&xinner, g_xinner);
    cudaGetSymbolAddress((void**)&xc,     g_xc);
    cudaGetSymbolAddress((void**)&delta,  g_delta);
    cudaGetSymbolAddress((void**)&Bm,     g_Bm);
    cudaGetSymbolAddress((void**)&Cm,     g_Cm);
    cudaGetSymbolAddress((void**)&y,      g_y);
    cudaGetSymbolAddress((void**)&ap,     g_ap);
    cudaGetSymbolAddress((void**)&he,     g_he);
    cudaGetSymbolAddress((void**)&xhi,    g_xhi);
    cudaGetSymbolAddress((void**)&xlo,    g_xlo);
    cudaGetSymbolAddress((void**)&whi,    g_whi);
    cudaGetSymbolAddress((void**)&wlo,    g_wlo);
    cudaGetSymbolAddress((void**)&yhi,    g_yhi);
    cudaGetSymbolAddress((void**)&ylo,    g_ylo);

    cudaFuncSetAttribute(hmma_gemm, cudaFuncAttributeMaxDynamicSharedMemorySize, SMEM_GEMM);

    /* split x and x_proj_w, then x_inner = x @ x_proj_w^T via HMMA */
    split_bf16<<<(NTOK*DMODEL/4 + 255)/256, 256>>>(x, xhi, xlo, NTOK*DMODEL/4);
    split_bf16<<<(DINNER*DMODEL/4 + 255)/256, 256>>>(x_proj_w, whi, wlo, DINNER*DMODEL/4);
    hmma_gemm<<<dim3(DINNER/128, NTOK/128), 256, SMEM_GEMM>>>(
        NTOK, DINNER, DMODEL, xhi, xlo, whi, wlo, xinner);

    /* delta_pre = x @ dt_proj_w^T */
    split_bf16<<<(DINNER*DMODEL/4 + 255)/256, 256>>>(dt_proj_w, whi, wlo, DINNER*DMODEL/4);
    hmma_gemm<<<dim3(DINNER/128, NTOK/128), 256, SMEM_GEMM>>>(
        NTOK, DINNER, DMODEL, xhi, xlo, whi, wlo, delta);

    /* B, C projections (N=16 each, fp32) */
    skinny_bc<<<NTOK/128, 256>>>(x, B_proj_w, C_proj_w, Bm, Cm);

    /* conv + SiLU -> xc ; softplus(delta + bias) in place */
    conv_silu_softplus<<<dim3(DINNER/256, SEQLEN/CTS, BATCH), 256>>>(
        xinner, conv_w, conv_b, dt_proj_b, xc, delta);

    /* chunked selective scan */
    scan_pass1<<<dim3(DINNER/128, NCH, BATCH), 128>>>(delta, xc, Bm, A_log, ap, he);
    scan_pass2<<<(BATCH*DINNER + 127)/128, 128>>>(ap, he);
    scan_pass3<<<dim3(DINNER/128, NCH, BATCH), 128>>>(delta, xc, Bm, Cm, A_log, Dvec, he, y);

    /* out = y @ out_proj_w^T via HMMA */
    split_bf16<<<(NTOK*DINNER/4 + 255)/256, 256>>>(y, yhi, ylo, NTOK*DINNER/4);
    split_bf16<<<(DMODEL*DINNER/4 + 255)/256, 256>>>(out_proj_w, whi, wlo, DMODEL*DINNER/4);
    hmma_gemm<<<dim3(DMODEL/128, NTOK/128), 256, SMEM_GEMM>>>(
        NTOK, DMODEL, DINNER, yhi, ylo, whi, wlo, out);
}

// round 4
// speedup vs baseline: 2.1086x; 1.0035x over previous
#include <cuda_runtime.h>
#include <cuda_bf16.h>
#include <math.h>
#include <stdint.h>

#define BATCH   4
#define SEQLEN  4096
#define DMODEL  1024
#define DINNER  2048
#define DSTATE  16
#define NTOK    (BATCH*SEQLEN)      /* 16384 */
#define CHUNK   256
#define NCH     (SEQLEN/CHUNK)      /* 16 */

/* ---------------- scratch (device globals; no allocation allowed) ---------------- */
__device__ float g_xinner[NTOK*DINNER];
__device__ float g_xc    [NTOK*DINNER];
__device__ float g_delta [NTOK*DINNER];
__device__ float g_Bm    [NTOK*DSTATE];
__device__ float g_Cm    [NTOK*DSTATE];
__device__ float g_ap    [BATCH*DINNER*NCH*DSTATE];
__device__ float g_he    [BATCH*DINNER*NCH*DSTATE];
__device__ __nv_bfloat16 g_xhi[NTOK*DMODEL];
__device__ __nv_bfloat16 g_xlo[NTOK*DMODEL];
__device__ __nv_bfloat16 g_whi[2*DINNER*DMODEL];   /* x_proj | dt_proj stacked */
__device__ __nv_bfloat16 g_wlo[2*DINNER*DMODEL];
__device__ __nv_bfloat16 g_w2hi[DMODEL*DINNER];    /* out_proj */
__device__ __nv_bfloat16 g_w2lo[DMODEL*DINNER];
__device__ __nv_bfloat16 g_yhi[NTOK*DINNER];
__device__ __nv_bfloat16 g_ylo[NTOK*DINNER];

/* ============================ PTX helpers ======================================== */
__device__ __forceinline__ uint32_t smem_u32(const void* p){
    uint32_t a;
    asm("{ .reg .u64 t; cvta.to.shared.u64 t, %1; cvt.u32.u64 %0, t; }" : "=r"(a) : "l"(p));
    return a;
}
__device__ __forceinline__ void cpa16(uint32_t dst, const void* src){
    asm volatile("cp.async.cg.shared.global [%0], [%1], 16;" :: "r"(dst), "l"(src));
}
__device__ __forceinline__ void ldsm4(uint32_t& r0, uint32_t& r1, uint32_t& r2, uint32_t& r3,
                                      uint32_t addr){
    asm volatile("ldmatrix.sync.aligned.m8n8.x4.shared.b16 {%0,%1,%2,%3}, [%4];"
                 : "=r"(r0), "=r"(r1), "=r"(r2), "=r"(r3) : "r"(addr));
}
__device__ __forceinline__ void ldsm2(uint32_t& r0, uint32_t& r1, uint32_t addr){
    asm volatile("ldmatrix.sync.aligned.m8n8.x2.shared.b16 {%0,%1}, [%2];"
                 : "=r"(r0), "=r"(r1) : "r"(addr));
}
__device__ __forceinline__ void mma16816(float* c, const uint32_t* a, const uint32_t* b){
    asm volatile(
        "mma.sync.aligned.m16n8k16.row.col.f32.bf16.bf16.f32 "
        "{%0,%1,%2,%3}, {%4,%5,%6,%7}, {%8,%9}, {%0,%1,%2,%3};"
        : "+f"(c[0]), "+f"(c[1]), "+f"(c[2]), "+f"(c[3])
        : "r"(a[0]), "r"(a[1]), "r"(a[2]), "r"(a[3]), "r"(b[0]), "r"(b[1]));
}

/* ====================== fp32 -> (bf16 hi, bf16 lo) split ========================= */
__global__ __launch_bounds__(256)
void split_bf16(const float* __restrict__ src,
                __nv_bfloat16* __restrict__ hi,
                __nv_bfloat16* __restrict__ lo, int n4)
{
    int i = blockIdx.x * 256 + threadIdx.x;
    if (i >= n4) return;
    float4 v = reinterpret_cast<const float4*>(src)[i];
    __nv_bfloat16 h0 = __float2bfloat16(v.x);
    __nv_bfloat16 h1 = __float2bfloat16(v.y);
    __nv_bfloat16 h2 = __float2bfloat16(v.z);
    __nv_bfloat16 h3 = __float2bfloat16(v.w);
    __nv_bfloat16 l0 = __float2bfloat16(v.x - __bfloat162float(h0));
    __nv_bfloat16 l1 = __float2bfloat16(v.y - __bfloat162float(h1));
    __nv_bfloat16 l2 = __float2bfloat16(v.z - __bfloat162float(h2));
    __nv_bfloat16 l3 = __float2bfloat16(v.w - __bfloat162float(h3));
    __nv_bfloat162* hp = reinterpret_cast<__nv_bfloat162*>(hi);
    __nv_bfloat162* lp = reinterpret_cast<__nv_bfloat162*>(lo);
    hp[2*i]   = __halves2bfloat162(h0, h1);
    hp[2*i+1] = __halves2bfloat162(h2, h3);
    lp[2*i]   = __halves2bfloat162(l0, l1);
    lp[2*i+1] = __halves2bfloat162(l2, l3);
}

/* ============ HMMA bf16x3 GEMM: C[M,N] = A[M,K] @ W[N,K]^T (fp32 out) ============ */
/* 128x128 CTA tile, BK=32, 4-stage cp.async pipeline, mma.sync m16n8k16.
   EPI=0: plain store to C0.
   EPI=1: fused x/dt epilogue — global col < DINNER -> C0 (xinner),
          else softplus(v + dtb[col-DINNER]) -> C1 (delta).                          */
#define ROWB      80                 /* 64B data + 16B pad, conflict-free ldmatrix  */
#define TILE_B    (128*ROWB)         /* 10240 */
#define STAGE_B   (4*TILE_B)         /* 40960: Ah, Al, Wh, Wl */
#define NSTAGE    4
#define SMEM_GEMM (NSTAGE*STAGE_B)   /* 163840 */

__device__ __forceinline__ void load_stage(
    uint32_t stage, int tid, int m0, int n0, int k0, int K,
    const __nv_bfloat16* __restrict__ Ah, const __nv_bfloat16* __restrict__ Al,
    const __nv_bfloat16* __restrict__ Wh, const __nv_bfloat16* __restrict__ Wl)
{
    #pragma unroll
    for (int i = 0; i < 8; ++i) {
        const int idx  = tid + 256 * i;
        const int tile = idx >> 9;          /* 512 chunks per tile */
        const int rem  = idx & 511;
        const int row  = rem >> 2;
        const int c    = rem & 3;
        const __nv_bfloat16* gp;
        if      (tile == 0) gp = Ah + (size_t)(m0 + row) * K + k0 + c*8;
        else if (tile == 1) gp = Al + (size_t)(m0 + row) * K + k0 + c*8;
        else if (tile == 2) gp = Wh + (size_t)(n0 + row) * K + k0 + c*8;
        else                gp = Wl + (size_t)(n0 + row) * K + k0 + c*8;
        cpa16(stage + tile * TILE_B + row * ROWB + c * 16, gp);
    }
    asm volatile("cp.async.commit_group;" ::: "memory");
}

template<int EPI>
__global__ void __launch_bounds__(256, 1)
hmma_gemm(int M, int N, int K,
          const __nv_bfloat16* __restrict__ Ah, const __nv_bfloat16* __restrict__ Al,
          const __nv_bfloat16* __restrict__ Wh, const __nv_bfloat16* __restrict__ Wl,
          float* __restrict__ C0, float* __restrict__ C1,
          const float* __restrict__ dtb)
{
    extern __shared__ char smem[];
    const uint32_t sb = smem_u32(smem);
    const int tid  = threadIdx.x;
    const int wid  = tid >> 5;
    const int lane = tid & 31;
    const int wy   = wid & 1;          /* 2 warps along M (64 rows each)  */
    const int wx   = wid >> 1;         /* 4 warps along N (32 cols each)  */
    const int m0 = blockIdx.y * 128, n0 = blockIdx.x * 128;

    float acc[4][4][4];
    #pragma unroll
    for (int i = 0; i < 4; ++i)
        #pragma unroll
        for (int j = 0; j < 4; ++j)
            #pragma unroll
            for (int e = 0; e < 4; ++e) acc[i][j][e] = 0.f;

    const int KT = K >> 5;

    load_stage(sb + 0*STAGE_B, tid, m0, n0,  0, K, Ah, Al, Wh, Wl);
    load_stage(sb + 1*STAGE_B, tid, m0, n0, 32, K, Ah, Al, Wh, Wl);
    load_stage(sb + 2*STAGE_B, tid, m0, n0, 64, K, Ah, Al, Wh, Wl);

    const int arow = lane & 15;
    const int acol = (lane >> 4) * 16;
    const int brow = lane & 7;
    const int bcol = ((lane >> 3) & 1) * 16;

    for (int kt = 0; kt < KT; ++kt) {
        asm volatile("cp.async.wait_group 2;" ::: "memory");
        __syncthreads();

        if (kt + 3 < KT)
            load_stage(sb + ((kt + 3) & 3) * STAGE_B, tid, m0, n0, (kt + 3) * 32,
                       K, Ah, Al, Wh, Wl);

        const uint32_t st = sb + (kt & 3) * STAGE_B;
        #pragma unroll
        for (int ks = 0; ks < 2; ++ks) {
            uint32_t ah[4][4], al[4][4], bh[4][2], bl[4][2];
            #pragma unroll
            for (int mi = 0; mi < 4; ++mi) {
                uint32_t ra = st + (uint32_t)((wy*64 + mi*16 + arow) * ROWB + ks*32 + acol);
                ldsm4(ah[mi][0], ah[mi][1], ah[mi][2], ah[mi][3], ra);
                ldsm4(al[mi][0], al[mi][1], al[mi][2], al[mi][3], ra + TILE_B);
            }
            #pragma unroll
            for (int ni = 0; ni < 4; ++ni) {
                uint32_t rb = st + 2*TILE_B +
                              (uint32_t)((wx*32 + ni*8 + brow) * ROWB + ks*32 + bcol);
                ldsm2(bh[ni][0], bh[ni][1], rb);
                ldsm2(bl[ni][0], bl[ni][1], rb + TILE_B);
            }
            #pragma unroll
            for (int mi = 0; mi < 4; ++mi)
                #pragma unroll
                for (int ni = 0; ni < 4; ++ni) {
                    mma16816(acc[mi][ni], ah[mi], bh[ni]);
                    mma16816(acc[mi][ni], ah[mi], bl[ni]);
                    mma16816(acc[mi][ni], al[mi], bh[ni]);
                }
        }
        /* no trailing sync: top-of-loop sync orders stage reuse (distance 3 < 4) */
    }

    /* epilogue */
    const int r0 = lane >> 2;
    const int c0 = (lane & 3) * 2;
    #pragma unroll
    for (int mi = 0; mi < 4; ++mi)
        #pragma unroll
        for (int ni = 0; ni < 4; ++ni) {
            const int row = m0 + wy*64 + mi*16 + r0;
            const int col = n0 + wx*32 + ni*8 + c0;
            if (EPI == 0) {
                *reinterpret_cast<float2*>(C0 + (size_t)row * N + col) =
                    make_float2(acc[mi][ni][0], acc[mi][ni][1]);
                *reinterpret_cast<float2*>(C0 + (size_t)(row + 8) * N + col) =
                    make_float2(acc[mi][ni][2], acc[mi][ni][3]);
            } else {
                if (col < DINNER) {
                    *reinterpret_cast<float2*>(C0 + (size_t)row * DINNER + col) =
                        make_float2(acc[mi][ni][0], acc[mi][ni][1]);
                    *reinterpret_cast<float2*>(C0 + (size_t)(row + 8) * DINNER + col) =
                        make_float2(acc[mi][ni][2], acc[mi][ni][3]);
                } else {
                    const int dc = col - DINNER;
                    const float b0 = dtb[dc], b1 = dtb[dc + 1];
                    float z0 = acc[mi][ni][0] + b0, z1 = acc[mi][ni][1] + b1;
                    float z2 = acc[mi][ni][2] + b0, z3 = acc[mi][ni][3] + b1;
                    z0 = (z0 > 20.f) ? z0 : log1pf(__expf(z0));
                    z1 = (z1 > 20.f) ? z1 : log1pf(__expf(z1));
                    z2 = (z2 > 20.f) ? z2 : log1pf(__expf(z2));
                    z3 = (z3 > 20.f) ? z3 : log1pf(__expf(z3));
                    *reinterpret_cast<float2*>(C1 + (size_t)row * DINNER + dc) =
                        make_float2(z0, z1);
                    *reinterpret_cast<float2*>(C1 + (size_t)(row + 8) * DINNER + dc) =
                        make_float2(z2, z3);
                }
            }
        }
}

/* ------------- skinny GEMM: B = X @ BW^T (N=16), C = X @ CW^T (N=16) ------------- */
__global__ __launch_bounds__(256)
void skinny_bc(const float* __restrict__ X,
               const float* __restrict__ BW,
               const float* __restrict__ CW,
               float* __restrict__ Bm,
               float* __restrict__ Cm)
{
    __shared__ float Xs[128][33];
    __shared__ float Ws[32][33];
    const int tid = threadIdx.x;
    const int n = tid & 31;
    const int g = tid >> 5;
    const int m0 = blockIdx.x * 128;

    float acc[16];
    #pragma unroll
    for (int i = 0; i < 16; ++i) acc[i] = 0.f;

    for (int k0 = 0; k0 < DMODEL; k0 += 32) {
        for (int f = tid; f < 1024; f += 256) {
            int r = f >> 3, c = (f & 7) * 4;
            float4 v = *reinterpret_cast<const float4*>(X + (size_t)(m0 + r) * DMODEL + k0 + c);
            Xs[r][c] = v.x; Xs[r][c+1] = v.y; Xs[r][c+2] = v.z; Xs[r][c+3] = v.w;
        }
        {
            int r = tid >> 3, c = (tid & 7) * 4;
            const float* src = (r < 16) ? (BW + (size_t)r * DMODEL)
                                        : (CW + (size_t)(r - 16) * DMODEL);
            float4 v = *reinterpret_cast<const float4*>(src + k0 + c);
            Ws[r][c] = v.x; Ws[r][c+1] = v.y; Ws[r][c+2] = v.z; Ws[r][c+3] = v.w;
        }
        __syncthreads();
        #pragma unroll
        for (int kk = 0; kk < 32; ++kk) {
            float w = Ws[n][kk];
            #pragma unroll
            for (int i = 0; i < 16; ++i)
                acc[i] = fmaf(Xs[g*16 + i][kk], w, acc[i]);
        }
        __syncthreads();
    }

    float* dst = (n < 16) ? Bm : Cm;
    const int nn = n & 15;
    #pragma unroll
    for (int i = 0; i < 16; ++i)
        dst[(size_t)(m0 + g*16 + i) * DSTATE + nn] = acc[i];
}

/* ---------------- depthwise causal conv1d + bias + SiLU -> xc -------------------- */
#define CTS 32
__global__ void conv_silu(const float* __restrict__ xin,
                          const float* __restrict__ cw,
                          const float* __restrict__ cb,
                          float* __restrict__ xc)
{
    const int d  = blockIdx.x * blockDim.x + threadIdx.x;
    const int b  = blockIdx.z;
    const int t0 = blockIdx.y * CTS;

    const float w0 = cw[d*4+0], w1 = cw[d*4+1], w2 = cw[d*4+2], w3 = cw[d*4+3];
    const float bias = cb[d];

    const float* base = xin + (size_t)b * SEQLEN * DINNER + d;
    float xm3 = (t0 - 3 >= 0) ? base[(size_t)(t0-3) * DINNER] : 0.f;
    float xm2 = (t0 - 2 >= 0) ? base[(size_t)(t0-2) * DINNER] : 0.f;
    float xm1 = (t0 - 1 >= 0) ? base[(size_t)(t0-1) * DINNER] : 0.f;

    #pragma unroll 4
    for (int t = t0; t < t0 + CTS; ++t) {
        float cur = base[(size_t)t * DINNER];
        float v = fmaf(w0, xm3, fmaf(w1, xm2, fmaf(w2, xm1, fmaf(w3, cur, bias))));
        float sig = 1.f / (1.f + __expf(-v));
        xc[((size_t)b * SEQLEN + t) * DINNER + d] = v * sig;
        xm3 = xm2; xm2 = xm1; xm1 = cur;
    }
}

/* --------------- scan pass 1: per-chunk decay products + local h_end ------------- */
__global__ __launch_bounds__(128)
void scan_pass1(const float* __restrict__ delta, const float* __restrict__ xc,
                const float* __restrict__ Bm, const float* __restrict__ A_log,
                float* __restrict__ ap_out, float* __restrict__ he_out)
{
    __shared__ float Bs[CHUNK*DSTATE];
    const int tid = threadIdx.x;
    const int d = blockIdx.x * 128 + tid;
    const int c = blockIdx.y, b = blockIdx.z;

    const float* Bsrc = Bm + ((size_t)b * SEQLEN + (size_t)c * CHUNK) * DSTATE;
    for (int i = tid; i < CHUNK*DSTATE; i += 128) Bs[i] = Bsrc[i];
    __syncthreads();

    float A[DSTATE];
    #pragma unroll
    for (int s = 0; s < DSTATE; ++s) A[s] = -expf(A_log[d*DSTATE + s]);

    float h[DSTATE], ap[DSTATE];
    #pragma unroll
    for (int s = 0; s < DSTATE; ++s) { h[s] = 0.f; ap[s] = 1.f; }

    const float* dptr = delta + ((size_t)b * SEQLEN + (size_t)c * CHUNK) * DINNER + d;
    const float* xptr = xc    + ((size_t)b * SEQLEN + (size_t)c * CHUNK) * DINNER + d;

    for (int tl = 0; tl < CHUNK; ++tl) {
        float dt = dptr[(size_t)tl * DINNER];
        float xv = xptr[(size_t)tl * DINNER];
        float dx = dt * xv;
        #pragma unroll
        for (int s = 0; s < DSTATE; ++s) {
            float a = __expf(dt * A[s]);
            ap[s] *= a;
            h[s] = fmaf(a, h[s], dx * Bs[tl*DSTATE + s]);
        }
    }

    const size_t o = (((size_t)b * DINNER + d) * NCH + c) * DSTATE;
    #pragma unroll
    for (int s = 0; s < DSTATE; ++s) { ap_out[o+s] = ap[s]; he_out[o+s] = h[s]; }
}

/* ------- scan pass 2: sequential stitch over chunks; he buffer -> chunk inits ---- */
__global__ void scan_pass2(const float* __restrict__ ap, float* __restrict__ he)
{
    const int idx = blockIdx.x * blockDim.x + threadIdx.x;
    if (idx >= BATCH*DINNER) return;
    float h[DSTATE];
    #pragma unroll
    for (int s = 0; s < DSTATE; ++s) h[s] = 0.f;
    for (int c = 0; c < NCH; ++c) {
        const size_t o = ((size_t)idx * NCH + c) * DSTATE;
        #pragma unroll
        for (int s = 0; s < DSTATE; ++s) {
            float hin = h[s];
            h[s] = fmaf(ap[o+s], hin, he[o+s]);
            he[o+s] = hin;
        }
    }
}

/* ----- scan pass 3: recompute with correct init, emit y as bf16 hi/lo pair ------- */
__global__ __launch_bounds__(128)
void scan_pass3(const float* __restrict__ delta, const float* __restrict__ xc,
                const float* __restrict__ Bm, const float* __restrict__ Cm,
                const float* __restrict__ A_log, const float* __restrict__ Dv,
                const float* __restrict__ hinit,
                __nv_bfloat16* __restrict__ yhi, __nv_bfloat16* __restrict__ ylo)
{
    __shared__ float Bs[CHUNK*DSTATE];
    __shared__ float Cs[CHUNK*DSTATE];
    const int tid = threadIdx.x;
    const int d = blockIdx.x * 128 + tid;
    const int c = blockIdx.y, b = blockIdx.z;

    const float* Bsrc = Bm + ((size_t)b * SEQLEN + (size_t)c * CHUNK) * DSTATE;
    const float* Csrc = Cm + ((size_t)b * SEQLEN + (size_t)c * CHUNK) * DSTATE;
    for (int i = tid; i < CHUNK*DSTATE; i += 128) { Bs[i] = Bsrc[i]; Cs[i] = Csrc[i]; }
    __syncthreads();

    float A[DSTATE];
    #pragma unroll
    for (int s = 0; s < DSTATE; ++s) A[s] = -expf(A_log[d*DSTATE + s]);

    float h[DSTATE];
    const size_t oinit = (((size_t)b * DINNER + d) * NCH + c) * DSTATE;
    #pragma unroll
    for (int s = 0; s < DSTATE; ++s) h[s] = hinit[oinit + s];

    const float Dd = Dv[d];
    const size_t tb = ((size_t)b * SEQLEN + (size_t)c * CHUNK) * DINNER + d;
    const float* dptr = delta + tb;
    const float* xptr = xc    + tb;

    for (int tl = 0; tl < CHUNK; ++tl) {
        float dt = dptr[(size_t)tl * DINNER];
        float xv = xptr[(size_t)tl * DINNER];
        float dx = dt * xv;
        float acc = 0.f;
        #pragma unroll
        for (int s = 0; s < DSTATE; ++s) {
            float a = __expf(dt * A[s]);
            h[s] = fmaf(a, h[s], dx * Bs[tl*DSTATE + s]);
            acc = fmaf(h[s], Cs[tl*DSTATE + s], acc);
        }
        float yv = fmaf(Dd, xv, acc);
        __nv_bfloat16 hb = __float2bfloat16(yv);
        __nv_bfloat16 lb = __float2bfloat16(yv - __bfloat162float(hb));
        yhi[tb + (size_t)tl * DINNER] = hb;
        ylo[tb + (size_t)tl * DINNER] = lb;
    }
}

/* -------------------------------- launcher --------------------------------------- */
extern "C" void kernel_launch(void* const* d_in, const int* in_sizes, int n_in,
                              void* d_out, int out_size)
{
    const float* x         = (const float*)d_in[0];
    const float* x_proj_w  = (const float*)d_in[1];
    const float* dt_proj_w = (const float*)d_in[2];
    const float* dt_proj_b = (const float*)d_in[3];
    const float* A_log     = (const float*)d_in[4];
    const float* Dvec      = (const float*)d_in[5];
    const float* B_proj_w  = (const float*)d_in[6];
    const float* C_proj_w  = (const float*)d_in[7];
    const float* conv_w    = (const float*)d_in[8];
    const float* conv_b    = (const float*)d_in[9];
    const float* out_proj_w= (const float*)d_in[10];
    float* out = (float*)d_out;

    float *xinner, *xc, *delta, *Bm, *Cm, *ap, *he;
    __nv_bfloat16 *xhi, *xlo, *whi, *wlo, *w2hi, *w2lo, *yhi, *ylo;
    cudaGetSymbolAddress((void**)&xinner, g_xinner);
    cudaGetSymbolAddress((void**)&xc,     g_xc);
    cudaGetSymbolAddress((void**)&delta,  g_delta);
    cudaGetSymbolAddress((void**)&Bm,     g_Bm);
    cudaGetSymbolAddress((void**)&Cm,     g_Cm);
    cudaGetSymbolAddress((void**)&ap,     g_ap);
    cudaGetSymbolAddress((void**)&he,     g_he);
    cudaGetSymbolAddress((void**)&xhi,    g_xhi);
    cudaGetSymbolAddress((void**)&xlo,    g_xlo);
    cudaGetSymbolAddress((void**)&whi,    g_whi);
    cudaGetSymbolAddress((void**)&wlo,    g_wlo);
    cudaGetSymbolAddress((void**)&w2hi,   g_w2hi);
    cudaGetSymbolAddress((void**)&w2lo,   g_w2lo);
    cudaGetSymbolAddress((void**)&yhi,    g_yhi);
    cudaGetSymbolAddress((void**)&ylo,    g_ylo);

    cudaFuncSetAttribute(hmma_gemm<0>, cudaFuncAttributeMaxDynamicSharedMemorySize, SMEM_GEMM);
    cudaFuncSetAttribute(hmma_gemm<1>, cudaFuncAttributeMaxDynamicSharedMemorySize, SMEM_GEMM);

    /* launches 1-5: splits + skinny (6th launch = big GEMM, targeted by ncu -s 5) */
    split_bf16<<<NTOK*DMODEL/4/256, 256>>>(x, xhi, xlo, NTOK*DMODEL/4);
    split_bf16<<<DINNER*DMODEL/4/256, 256>>>(x_proj_w, whi, wlo, DINNER*DMODEL/4);
    split_bf16<<<DINNER*DMODEL/4/256, 256>>>(dt_proj_w, whi + DINNER*DMODEL,
                                             wlo + DINNER*DMODEL, DINNER*DMODEL/4);
    skinny_bc<<<NTOK/128, 256>>>(x, B_proj_w, C_proj_w, Bm, Cm);
    split_bf16<<<DMODEL*DINNER/4/256, 256>>>(out_proj_w, w2hi, w2lo, DMODEL*DINNER/4);

    /* fused x_proj+dt_proj GEMM: N=4096, epilogue splits xinner / softplus(delta) */
    hmma_gemm<1><<<dim3(2*DINNER/128, NTOK/128), 256, SMEM_GEMM>>>(
        NTOK, 2*DINNER, DMODEL, xhi, xlo, whi, wlo, xinner, delta, dt_proj_b);

    /* conv + SiLU -> xc */
    conv_silu<<<dim3(DINNER/256, SEQLEN/CTS, BATCH), 256>>>(xinner, conv_w, conv_b, xc);

    /* chunked selective scan (pass3 emits bf16 hi/lo directly) */
    scan_pass1<<<dim3(DINNER/128, NCH, BATCH), 128>>>(delta, xc, Bm, A_log, ap, he);
    scan_pass2<<<(BATCH*DINNER + 127)/128, 128>>>(ap, he);
    scan_pass3<<<dim3(DINNER/128, NCH, BATCH), 128>>>(delta, xc, Bm, Cm, A_log, Dvec,
                                                      he, yhi, ylo);

    /* out = y @ out_proj_w^T */
    hmma_gemm<0><<<dim3(DMODEL/128, NTOK/128), 256, SMEM_GEMM>>>(
        NTOK, DMODEL, DINNER, yhi, ylo, w2hi, w2lo, out, nullptr, nullptr);
}

// round 5
// speedup vs baseline: 2.2155x; 1.0507x over previous
#include <cuda_runtime.h>
#include <cuda_bf16.h>
#include <math.h>
#include <stdint.h>

#define BATCH   4
#define SEQLEN  4096
#define DMODEL  1024
#define DINNER  2048
#define DSTATE  16
#define NTOK    (BATCH*SEQLEN)      /* 16384 */
#define CHUNK   256
#define NCH     (SEQLEN/CHUNK)      /* 16 */

/* ---------------- scratch (device globals; no allocation allowed) ---------------- */
__device__ float g_xinner[NTOK*DINNER];
__device__ float g_xc    [NTOK*DINNER];
__device__ float g_delta [NTOK*DINNER];
__device__ float g_Bm    [NTOK*DSTATE];
__device__ float g_Cm    [NTOK*DSTATE];
__device__ float g_ap    [BATCH*DINNER*NCH*DSTATE];
__device__ float g_he    [BATCH*DINNER*NCH*DSTATE];
__device__ __nv_bfloat16 g_xhi[NTOK*DMODEL];
__device__ __nv_bfloat16 g_xlo[NTOK*DMODEL];
__device__ __nv_bfloat16 g_whi[2*DINNER*DMODEL];   /* x_proj | dt_proj stacked */
__device__ __nv_bfloat16 g_wlo[2*DINNER*DMODEL];
__device__ __nv_bfloat16 g_w2hi[DMODEL*DINNER];    /* out_proj */
__device__ __nv_bfloat16 g_w2lo[DMODEL*DINNER];
__device__ __nv_bfloat16 g_yhi[NTOK*DINNER];
__device__ __nv_bfloat16 g_ylo[NTOK*DINNER];

/* ============================ PTX helpers ======================================== */
__device__ __forceinline__ uint32_t smem_u32(const void* p){
    uint32_t a;
    asm("{ .reg .u64 t; cvta.to.shared.u64 t, %1; cvt.u32.u64 %0, t; }" : "=r"(a) : "l"(p));
    return a;
}
__device__ __forceinline__ void cpa16(uint32_t dst, const void* src){
    asm volatile("cp.async.cg.shared.global [%0], [%1], 16;" :: "r"(dst), "l"(src));
}
__device__ __forceinline__ void ldsm4(uint32_t& r0, uint32_t& r1, uint32_t& r2, uint32_t& r3,
                                      uint32_t addr){
    asm volatile("ldmatrix.sync.aligned.m8n8.x4.shared.b16 {%0,%1,%2,%3}, [%4];"
                 : "=r"(r0), "=r"(r1), "=r"(r2), "=r"(r3) : "r"(addr));
}
__device__ __forceinline__ void mma16816(float* c, const uint32_t* a, const uint32_t* b){
    asm volatile(
        "mma.sync.aligned.m16n8k16.row.col.f32.bf16.bf16.f32 "
        "{%0,%1,%2,%3}, {%4,%5,%6,%7}, {%8,%9}, {%0,%1,%2,%3};"
        : "+f"(c[0]), "+f"(c[1]), "+f"(c[2]), "+f"(c[3])
        : "r"(a[0]), "r"(a[1]), "r"(a[2]), "r"(a[3]), "r"(b[0]), "r"(b[1]));
}

/* ====================== fp32 -> (bf16 hi, bf16 lo) split ========================= */
__global__ __launch_bounds__(256)
void split_bf16(const float* __restrict__ src,
                __nv_bfloat16* __restrict__ hi,
                __nv_bfloat16* __restrict__ lo, int n4)
{
    int i = blockIdx.x * 256 + threadIdx.x;
    if (i >= n4) return;
    float4 v = reinterpret_cast<const float4*>(src)[i];
    __nv_bfloat16 h0 = __float2bfloat16(v.x);
    __nv_bfloat16 h1 = __float2bfloat16(v.y);
    __nv_bfloat16 h2 = __float2bfloat16(v.z);
    __nv_bfloat16 h3 = __float2bfloat16(v.w);
    __nv_bfloat16 l0 = __float2bfloat16(v.x - __bfloat162float(h0));
    __nv_bfloat16 l1 = __float2bfloat16(v.y - __bfloat162float(h1));
    __nv_bfloat16 l2 = __float2bfloat16(v.z - __bfloat162float(h2));
    __nv_bfloat16 l3 = __float2bfloat16(v.w - __bfloat162float(h3));
    __nv_bfloat162* hp = reinterpret_cast<__nv_bfloat162*>(hi);
    __nv_bfloat162* lp = reinterpret_cast<__nv_bfloat162*>(lo);
    hp[2*i]   = __halves2bfloat162(h0, h1);
    hp[2*i+1] = __halves2bfloat162(h2, h3);
    lp[2*i]   = __halves2bfloat162(l0, l1);
    lp[2*i+1] = __halves2bfloat162(l2, l3);
}

/* ============ HMMA bf16x3 GEMM: C[M,N] = A[M,K] @ W[N,K]^T (fp32 out) ============ */
/* CTA tile 256x128, warp tile 64x64 (8 warps: 4 along M, 2 along N), BK=32,
   3-stage cp.async pipeline, mma.sync m16n8k16, hi/lo split (3 MMAs / output).     */
#define ROWB      80                 /* 64B data + 16B pad, conflict-free ldmatrix  */
#define A_TILE    (256*ROWB)         /* 20480 */
#define B_TILE    (128*ROWB)         /* 10240 */
#define STAGE_B   (2*A_TILE + 2*B_TILE)   /* 61440: Ah, Al, Wh, Wl */
#define NSTAGE    3
#define SMEM_GEMM (NSTAGE*STAGE_B)   /* 184320 */

__device__ __forceinline__ void load_stage(
    uint32_t stage, int tid, int m0, int n0, int k0, int K,
    const __nv_bfloat16* __restrict__ Ah, const __nv_bfloat16* __restrict__ Al,
    const __nv_bfloat16* __restrict__ Wh, const __nv_bfloat16* __restrict__ Wl)
{
    /* A: 256 rows x 4 16B-chunks, hi+lo = 2048 chunks */
    #pragma unroll
    for (int j = 0; j < 8; ++j) {
        const int idx  = tid + 256 * j;
        const int half = idx >> 10;
        const int rem  = idx & 1023;
        const int row  = rem >> 2;
        const int c    = rem & 3;
        const __nv_bfloat16* gp = (half ? Al : Ah) + (size_t)(m0 + row) * K + k0 + c*8;
        cpa16(stage + half * A_TILE + row * ROWB + c * 16, gp);
    }
    /* B: 128 rows x 4 chunks, hi+lo = 1024 chunks */
    #pragma unroll
    for (int j = 0; j < 4; ++j) {
        const int idx  = tid + 256 * j;
        const int half = idx >> 9;
        const int rem  = idx & 511;
        const int row  = rem >> 2;
        const int c    = rem & 3;
        const __nv_bfloat16* gp = (half ? Wl : Wh) + (size_t)(n0 + row) * K + k0 + c*8;
        cpa16(stage + 2 * A_TILE + half * B_TILE + row * ROWB + c * 16, gp);
    }
    asm volatile("cp.async.commit_group;" ::: "memory");
}

template<int EPI>
__global__ void __launch_bounds__(256, 1)
hmma_gemm(int M, int N, int K,
          const __nv_bfloat16* __restrict__ Ah, const __nv_bfloat16* __restrict__ Al,
          const __nv_bfloat16* __restrict__ Wh, const __nv_bfloat16* __restrict__ Wl,
          float* __restrict__ C0, float* __restrict__ C1,
          const float* __restrict__ dtb)
{
    extern __shared__ char smem[];
    const uint32_t sb = smem_u32(smem);
    const int tid  = threadIdx.x;
    const int wid  = tid >> 5;
    const int lane = tid & 31;
    const int wy   = wid & 3;          /* 4 warps along M (64 rows each)  */
    const int wx   = wid >> 2;         /* 2 warps along N (64 cols each)  */
    const int m0 = blockIdx.y * 256, n0 = blockIdx.x * 128;

    float acc[4][8][4];
    #pragma unroll
    for (int i = 0; i < 4; ++i)
        #pragma unroll
        for (int j = 0; j < 8; ++j)
            #pragma unroll
            for (int e = 0; e < 4; ++e) acc[i][j][e] = 0.f;

    const int KT = K >> 5;

    load_stage(sb + 0*STAGE_B, tid, m0, n0,  0, K, Ah, Al, Wh, Wl);
    load_stage(sb + 1*STAGE_B, tid, m0, n0, 32, K, Ah, Al, Wh, Wl);

    /* ldmatrix per-lane address components */
    const int arow = lane & 15;                          /* A row-within-16      */
    const int acol = (lane >> 4) * 16;                   /* A k-half selector    */
    const int brow = (lane & 7) + ((lane >> 4) << 3);    /* B: n-within-16       */
    const int bcol = ((lane >> 3) & 1) * 16;             /* B k-half selector    */

    for (int kt = 0; kt < KT; ++kt) {
        if (kt + 1 < KT) asm volatile("cp.async.wait_group 1;" ::: "memory");
        else             asm volatile("cp.async.wait_group 0;" ::: "memory");
        __syncthreads();

        if (kt + 2 < KT)
            load_stage(sb + ((kt + 2) % 3) * STAGE_B, tid, m0, n0, (kt + 2) * 32,
                       K, Ah, Al, Wh, Wl);

        const uint32_t st  = sb + (kt % 3) * STAGE_B;
        const uint32_t stb = st + 2 * A_TILE;
        #pragma unroll
        for (int ks = 0; ks < 2; ++ks) {
            uint32_t ah[4][4], al[4][4], bh[8][2], bl[8][2];
            #pragma unroll
            for (int mi = 0; mi < 4; ++mi) {
                uint32_t ra = st + (uint32_t)((wy*64 + mi*16 + arow) * ROWB + ks*32 + acol);
                ldsm4(ah[mi][0], ah[mi][1], ah[mi][2], ah[mi][3], ra);
                ldsm4(al[mi][0], al[mi][1], al[mi][2], al[mi][3], ra + A_TILE);
            }
            #pragma unroll
            for (int p = 0; p < 4; ++p) {   /* each ldsm4 covers n8 pair (2p,2p+1) */
                uint32_t rb = stb + (uint32_t)((wx*64 + p*16 + brow) * ROWB + ks*32 + bcol);
                ldsm4(bh[2*p][0], bh[2*p][1], bh[2*p+1][0], bh[2*p+1][1], rb);
                ldsm4(bl[2*p][0], bl[2*p][1], bl[2*p+1][0], bl[2*p+1][1], rb + B_TILE);
            }
            #pragma unroll
            for (int mi = 0; mi < 4; ++mi)
                #pragma unroll
                for (int ni = 0; ni < 8; ++ni) {
                    mma16816(acc[mi][ni], ah[mi], bh[ni]);
                    mma16816(acc[mi][ni], ah[mi], bl[ni]);
                    mma16816(acc[mi][ni], al[mi], bh[ni]);
                }
        }
        /* no trailing sync: top-of-loop sync orders stage reuse */
    }

    /* epilogue */
    const int r0 = lane >> 2;
    const int c0 = (lane & 3) * 2;
    #pragma unroll
    for (int mi = 0; mi < 4; ++mi)
        #pragma unroll
        for (int ni = 0; ni < 8; ++ni) {
            const int row = m0 + wy*64 + mi*16 + r0;
            const int col = n0 + wx*64 + ni*8 + c0;
            if (EPI == 0) {
                *reinterpret_cast<float2*>(C0 + (size_t)row * N + col) =
                    make_float2(acc[mi][ni][0], acc[mi][ni][1]);
                *reinterpret_cast<float2*>(C0 + (size_t)(row + 8) * N + col) =
                    make_float2(acc[mi][ni][2], acc[mi][ni][3]);
            } else {
                if (col < DINNER) {
                    *reinterpret_cast<float2*>(C0 + (size_t)row * DINNER + col) =
                        make_float2(acc[mi][ni][0], acc[mi][ni][1]);
                    *reinterpret_cast<float2*>(C0 + (size_t)(row + 8) * DINNER + col) =
                        make_float2(acc[mi][ni][2], acc[mi][ni][3]);
                } else {
                    const int dc = col - DINNER;
                    const float b0 = dtb[dc], b1 = dtb[dc + 1];
                    float z0 = acc[mi][ni][0] + b0, z1 = acc[mi][ni][1] + b1;
                    float z2 = acc[mi][ni][2] + b0, z3 = acc[mi][ni][3] + b1;
                    z0 = (z0 > 20.f) ? z0 : log1pf(__expf(z0));
                    z1 = (z1 > 20.f) ? z1 : log1pf(__expf(z1));
                    z2 = (z2 > 20.f) ? z2 : log1pf(__expf(z2));
                    z3 = (z3 > 20.f) ? z3 : log1pf(__expf(z3));
                    *reinterpret_cast<float2*>(C1 + (size_t)row * DINNER + dc) =
                        make_float2(z0, z1);
                    *reinterpret_cast<float2*>(C1 + (size_t)(row + 8) * DINNER + dc) =
                        make_float2(z2, z3);
                }
            }
        }
}

/* ------------- skinny GEMM: B = X @ BW^T (N=16), C = X @ CW^T (N=16) ------------- */
/* 32 tokens/CTA -> grid 512, 4 outputs/thread                                      */
__global__ __launch_bounds__(256)
void skinny_bc(const float* __restrict__ X,
               const float* __restrict__ BW,
               const float* __restrict__ CW,
               float* __restrict__ Bm,
               float* __restrict__ Cm)
{
    __shared__ float Xs[32][33];
    __shared__ float Ws[32][33];
    const int tid = threadIdx.x;
    const int n = tid & 31;       /* output col: B 0-15, C 16-31 */
    const int g = tid >> 5;       /* token group 0..7 (4 tokens) */
    const int m0 = blockIdx.x * 32;

    float acc[4];
    #pragma unroll
    for (int i = 0; i < 4; ++i) acc[i] = 0.f;

    for (int k0 = 0; k0 < DMODEL; k0 += 32) {
        {
            int r = tid >> 3, c = (tid & 7) * 4;
            float4 v = *reinterpret_cast<const float4*>(X + (size_t)(m0 + r) * DMODEL + k0 + c);
            Xs[r][c] = v.x; Xs[r][c+1] = v.y; Xs[r][c+2] = v.z; Xs[r][c+3] = v.w;
            const float* src = (r < 16) ? (BW + (size_t)r * DMODEL)
                                        : (CW + (size_t)(r - 16) * DMODEL);
            float4 w = *reinterpret_cast<const float4*>(src + k0 + c);
            Ws[r][c] = w.x; Ws[r][c+1] = w.y; Ws[r][c+2] = w.z; Ws[r][c+3] = w.w;
        }
        __syncthreads();
        #pragma unroll
        for (int kk = 0; kk < 32; ++kk) {
            float w = Ws[n][kk];
            #pragma unroll
            for (int i = 0; i < 4; ++i)
                acc[i] = fmaf(Xs[g*4 + i][kk], w, acc[i]);
        }
        __syncthreads();
    }

    float* dst = (n < 16) ? Bm : Cm;
    const int nn = n & 15;
    #pragma unroll
    for (int i = 0; i < 4; ++i)
        dst[(size_t)(m0 + g*4 + i) * DSTATE + nn] = acc[i];
}

/* ---------------- depthwise causal conv1d + bias + SiLU -> xc -------------------- */
#define CTS 32
__global__ void conv_silu(const float* __restrict__ xin,
                          const float* __restrict__ cw,
                          const float* __restrict__ cb,
                          float* __restrict__ xc)
{
    const int d  = blockIdx.x * blockDim.x + threadIdx.x;
    const int b  = blockIdx.z;
    const int t0 = blockIdx.y * CTS;

    const float w0 = cw[d*4+0], w1 = cw[d*4+1], w2 = cw[d*4+2], w3 = cw[d*4+3];
    const float bias = cb[d];

    const float* base = xin + (size_t)b * SEQLEN * DINNER + d;
    float xm3 = (t0 - 3 >= 0) ? base[(size_t)(t0-3) * DINNER] : 0.f;
    float xm2 = (t0 - 2 >= 0) ? base[(size_t)(t0-2) * DINNER] : 0.f;
    float xm1 = (t0 - 1 >= 0) ? base[(size_t)(t0-1) * DINNER] : 0.f;

    #pragma unroll 4
    for (int t = t0; t < t0 + CTS; ++t) {
        float cur = base[(size_t)t * DINNER];
        float v = fmaf(w0, xm3, fmaf(w1, xm2, fmaf(w2, xm1, fmaf(w3, cur, bias))));
        float sig = 1.f / (1.f + __expf(-v));
        xc[((size_t)b * SEQLEN + t) * DINNER + d] = v * sig;
        xm3 = xm2; xm2 = xm1; xm1 = cur;
    }
}

/* --------------- scan pass 1: per-chunk decay products + local h_end ------------- */
__global__ __launch_bounds__(128)
void scan_pass1(const float* __restrict__ delta, const float* __restrict__ xc,
                const float* __restrict__ Bm, const float* __restrict__ A_log,
                float* __restrict__ ap_out, float* __restrict__ he_out)
{
    __shared__ float Bs[CHUNK*DSTATE];
    const int tid = threadIdx.x;
    const int d = blockIdx.x * 128 + tid;
    const int c = blockIdx.y, b = blockIdx.z;

    const float* Bsrc = Bm + ((size_t)b * SEQLEN + (size_t)c * CHUNK) * DSTATE;
    for (int i = tid; i < CHUNK*DSTATE; i += 128) Bs[i] = Bsrc[i];
    __syncthreads();

    float A[DSTATE];
    #pragma unroll
    for (int s = 0; s < DSTATE; ++s) A[s] = -expf(A_log[d*DSTATE + s]);

    float h[DSTATE], ap[DSTATE];
    #pragma unroll
    for (int s = 0; s < DSTATE; ++s) { h[s] = 0.f; ap[s] = 1.f; }

    const float* dptr = delta + ((size_t)b * SEQLEN + (size_t)c * CHUNK) * DINNER + d;
    const float* xptr = xc    + ((size_t)b * SEQLEN + (size_t)c * CHUNK) * DINNER + d;

    for (int tl = 0; tl < CHUNK; ++tl) {
        float dt = dptr[(size_t)tl * DINNER];
        float xv = xptr[(size_t)tl * DINNER];
        float dx = dt * xv;
        #pragma unroll
        for (int s = 0; s < DSTATE; ++s) {
            float a = __expf(dt * A[s]);
            ap[s] *= a;
            h[s] = fmaf(a, h[s], dx * Bs[tl*DSTATE + s]);
        }
    }

    const size_t o = (((size_t)b * DINNER + d) * NCH + c) * DSTATE;
    #pragma unroll
    for (int s = 0; s < DSTATE; ++s) { ap_out[o+s] = ap[s]; he_out[o+s] = h[s]; }
}

/* ------- scan pass 2: sequential stitch over chunks; he buffer -> chunk inits ---- */
__global__ void scan_pass2(const float* __restrict__ ap, float* __restrict__ he)
{
    const int idx = blockIdx.x * blockDim.x + threadIdx.x;
    if (idx >= BATCH*DINNER) return;
    float h[DSTATE];
    #pragma unroll
    for (int s = 0; s < DSTATE; ++s) h[s] = 0.f;
    for (int c = 0; c < NCH; ++c) {
        const size_t o = ((size_t)idx * NCH + c) * DSTATE;
        #pragma unroll
        for (int s = 0; s < DSTATE; ++s) {
            float hin = h[s];
            h[s] = fmaf(ap[o+s], hin, he[o+s]);
            he[o+s] = hin;
        }
    }
}

/* ----- scan pass 3: recompute with correct init, emit y as bf16 hi/lo pair ------- */
__global__ __launch_bounds__(128)
void scan_pass3(const float* __restrict__ delta, const float* __restrict__ xc,
                const float* __restrict__ Bm, const float* __restrict__ Cm,
                const float* __restrict__ A_log, const float* __restrict__ Dv,
                const float* __restrict__ hinit,
                __nv_bfloat16* __restrict__ yhi, __nv_bfloat16* __restrict__ ylo)
{
    __shared__ float Bs[CHUNK*DSTATE];
    __shared__ float Cs[CHUNK*DSTATE];
    const int tid = threadIdx.x;
    const int d = blockIdx.x * 128 + tid;
    const int c = blockIdx.y, b = blockIdx.z;

    const float* Bsrc = Bm + ((size_t)b * SEQLEN + (size_t)c * CHUNK) * DSTATE;
    const float* Csrc = Cm + ((size_t)b * SEQLEN + (size_t)c * CHUNK) * DSTATE;
    for (int i = tid; i < CHUNK*DSTATE; i += 128) { Bs[i] = Bsrc[i]; Cs[i] = Csrc[i]; }
    __syncthreads();

    float A[DSTATE];
    #pragma unroll
    for (int s = 0; s < DSTATE; ++s) A[s] = -expf(A_log[d*DSTATE + s]);

    float h[DSTATE];
    const size_t oinit = (((size_t)b * DINNER + d) * NCH + c) * DSTATE;
    #pragma unroll
    for (int s = 0; s < DSTATE; ++s) h[s] = hinit[oinit + s];

    const float Dd = Dv[d];
    const size_t tb = ((size_t)b * SEQLEN + (size_t)c * CHUNK) * DINNER + d;
    const float* dptr = delta + tb;
    const float* xptr = xc    + tb;

    for (int tl = 0; tl < CHUNK; ++tl) {
        float dt = dptr[(size_t)tl * DINNER];
        float xv = xptr[(size_t)tl * DINNER];
        float dx = dt * xv;
        float acc = 0.f;
        #pragma unroll
        for (int s = 0; s < DSTATE; ++s) {
            float a = __expf(dt * A[s]);
            h[s] = fmaf(a, h[s], dx * Bs[tl*DSTATE + s]);
            acc = fmaf(h[s], Cs[tl*DSTATE + s], acc);
        }
        float yv = fmaf(Dd, xv, acc);
        __nv_bfloat16 hb = __float2bfloat16(yv);
        __nv_bfloat16 lb = __float2bfloat16(yv - __bfloat162float(hb));
        yhi[tb + (size_t)tl * DINNER] = hb;
        ylo[tb + (size_t)tl * DINNER] = lb;
    }
}

/* -------------------------------- launcher --------------------------------------- */
extern "C" void kernel_launch(void* const* d_in, const int* in_sizes, int n_in,
                              void* d_out, int out_size)
{
    const float* x         = (const float*)d_in[0];
    const float* x_proj_w  = (const float*)d_in[1];
    const float* dt_proj_w = (const float*)d_in[2];
    const float* dt_proj_b = (const float*)d_in[3];
    const float* A_log     = (const float*)d_in[4];
    const float* Dvec      = (const float*)d_in[5];
    const float* B_proj_w  = (const float*)d_in[6];
    const float* C_proj_w  = (const float*)d_in[7];
    const float* conv_w    = (const float*)d_in[8];
    const float* conv_b    = (const float*)d_in[9];
    const float* out_proj_w= (const float*)d_in[10];
    float* out = (float*)d_out;

    float *xinner, *xc, *delta, *Bm, *Cm, *ap, *he;
    __nv_bfloat16 *xhi, *xlo, *whi, *wlo, *w2hi, *w2lo, *yhi, *ylo;
    cudaGetSymbolAddress((void**)&xinner, g_xinner);
    cudaGetSymbolAddress((void**)&xc,     g_xc);
    cudaGetSymbolAddress((void**)&delta,  g_delta);
    cudaGetSymbolAddress((void**)&Bm,     g_Bm);
    cudaGetSymbolAddress((void**)&Cm,     g_Cm);
    cudaGetSymbolAddress((void**)&ap,     g_ap);
    cudaGetSymbolAddress((void**)&he,     g_he);
    cudaGetSymbolAddress((void**)&xhi,    g_xhi);
    cudaGetSymbolAddress((void**)&xlo,    g_xlo);
    cudaGetSymbolAddress((void**)&whi,    g_whi);
    cudaGetSymbolAddress((void**)&wlo,    g_wlo);
    cudaGetSymbolAddress((void**)&w2hi,   g_w2hi);
    cudaGetSymbolAddress((void**)&w2lo,   g_w2lo);
    cudaGetSymbolAddress((void**)&yhi,    g_yhi);
    cudaGetSymbolAddress((void**)&ylo,    g_ylo);

    cudaFuncSetAttribute(hmma_gemm<0>, cudaFuncAttributeMaxDynamicSharedMemorySize, SMEM_GEMM);
    cudaFuncSetAttribute(hmma_gemm<1>, cudaFuncAttributeMaxDynamicSharedMemorySize, SMEM_GEMM);

    split_bf16<<<NTOK*DMODEL/4/256, 256>>>(x, xhi, xlo, NTOK*DMODEL/4);
    split_bf16<<<DINNER*DMODEL/4/256, 256>>>(x_proj_w, whi, wlo, DINNER*DMODEL/4);
    split_bf16<<<DINNER*DMODEL/4/256, 256>>>(dt_proj_w, whi + DINNER*DMODEL,
                                             wlo + DINNER*DMODEL, DINNER*DMODEL/4);
    skinny_bc<<<NTOK/32, 256>>>(x, B_proj_w, C_proj_w, Bm, Cm);
    split_bf16<<<DMODEL*DINNER/4/256, 256>>>(out_proj_w, w2hi, w2lo, DMODEL*DINNER/4);

    /* fused x_proj+dt_proj GEMM: N=4096, epilogue splits xinner / softplus(delta) */
    hmma_gemm<1><<<dim3(2*DINNER/128, NTOK/256), 256, SMEM_GEMM>>>(
        NTOK, 2*DINNER, DMODEL, xhi, xlo, whi, wlo, xinner, delta, dt_proj_b);

    /* conv + SiLU -> xc */
    conv_silu<<<dim3(DINNER/256, SEQLEN/CTS, BATCH), 256>>>(xinner, conv_w, conv_b, xc);

    /* chunked selective scan (pass3 emits bf16 hi/lo directly) */
    scan_pass1<<<dim3(DINNER/128, NCH, BATCH), 128>>>(delta, xc, Bm, A_log, ap, he);
    scan_pass2<<<(BATCH*DINNER + 127)/128, 128>>>(ap, he);
    scan_pass3<<<dim3(DINNER/128, NCH, BATCH), 128>>>(delta, xc, Bm, Cm, A_log, Dvec,
                                                      he, yhi, ylo);

    /* out = y @ out_proj_w^T */
    hmma_gemm<0><<<dim3(DMODEL/128, NTOK/256), 256, SMEM_GEMM>>>(
        NTOK, DMODEL, DINNER, yhi, ylo, w2hi, w2lo, out, nullptr, nullptr);
}